// round 2
// baseline (speedup 1.0000x reference)
#include <cuda_runtime.h>
#include <math.h>

#define D_IN   1024
#define D_H    2048
#define BATCH  256
#define D_OUT  1000
#define ALPHA  0.5f
#define EPSV   1e-12f
#define STEPS  30

// ---------------- device scratch (no allocations allowed) ----------------
__device__ float g_t[D_IN];            // W_in^T @ u (pre-norm)
__device__ float g_s[D_H];             // W_in @ v
__device__ float g_scal[4];            // [0]=1/(||t||+eps), [1]=1/sigma
__device__ float g_xproj[BATCH * D_H];
__device__ float g_hA[BATCH * D_H];
__device__ float g_hB[BATCH * D_H];

// ---------------- small kernels: spectral norm scalar ----------------
__global__ void zero_kernel(float* p, int n) {
    int i = blockIdx.x * blockDim.x + threadIdx.x;
    if (i < n) p[i] = 0.0f;
}

// t[j] = sum_i W[i, j] * u[i]   (W is [D_H, D_IN] row-major)
__global__ void matvec_t_kernel(const float* __restrict__ W,
                                const float* __restrict__ u,
                                float* __restrict__ t) {
    int j = blockIdx.x * blockDim.x + threadIdx.x;
    if (j >= D_IN) return;
    float acc = 0.0f;
#pragma unroll 4
    for (int i = 0; i < D_H; i++)
        acc = fmaf(W[(size_t)i * D_IN + j], u[i], acc);
    t[j] = acc;
}

// scal[0] = 1 / (||t|| + eps)     (deterministic tree reduce)
__global__ void reduce_t_kernel(const float* __restrict__ t, float* __restrict__ scal) {
    __shared__ float sh[1024];
    int tid = threadIdx.x;
    float v = t[tid];
    sh[tid] = v * v;
    __syncthreads();
    for (int o = 512; o > 0; o >>= 1) {
        if (tid < o) sh[tid] += sh[tid + o];
        __syncthreads();
    }
    if (tid == 0) scal[0] = 1.0f / (sqrtf(sh[0]) + EPSV);
}

// s[r] = scal[0] * sum_j W[r, j] * t[j]   (one warp per row)
__global__ void matvec_s_kernel(const float* __restrict__ W,
                                const float* __restrict__ t,
                                const float* __restrict__ scal,
                                float* __restrict__ s) {
    int gtid = blockIdx.x * blockDim.x + threadIdx.x;
    int warp = gtid >> 5;
    int lane = gtid & 31;
    float invn = scal[0];
    for (int r = warp; r < D_H; r += 512) {
        const float* row = W + (size_t)r * D_IN;
        float acc = 0.0f;
        for (int j = lane; j < D_IN; j += 32)
            acc = fmaf(row[j], t[j], acc);
#pragma unroll
        for (int o = 16; o > 0; o >>= 1)
            acc += __shfl_xor_sync(0xffffffffu, acc, o);
        if (lane == 0) s[r] = acc * invn;
    }
}

// scal[1] = 1/sigma = (||s|| + eps) / ||s||^2   (deterministic)
__global__ void reduce_s_kernel(const float* __restrict__ s, float* __restrict__ scal) {
    __shared__ float sh[1024];
    int tid = threadIdx.x;
    float a = s[tid];
    float b = s[tid + 1024];
    sh[tid] = a * a + b * b;
    __syncthreads();
    for (int o = 512; o > 0; o >>= 1) {
        if (tid < o) sh[tid] += sh[tid + o];
        __syncthreads();
    }
    if (tid == 0) {
        float q = sh[0];                   // ||s||^2
        scal[1] = (sqrtf(q) + EPSV) / q;   // 1/sigma
    }
}

// ---------------- tiled fp32 GEMM-NT with fused epilogues ----------------
// C[m,n] = epilogue( sum_k A[m,k] * B[n,k] )
// MODE 0: C = acc * (*scale_ptr) + bias[n]                           (x_proj)
// MODE 1: C = (1-A)*hold + A*tanh(xproj + acc + bias[n])             (step)
// MODE 2: C = acc + bias[n]                                          (head)
// BM=BN=64, BK=16, 256 threads, 4x4 per thread. M % 64 == 0, K % 16 == 0.
template <int MODE>
__global__ void __launch_bounds__(256)
gemm_nt_kernel(const float* __restrict__ A, const float* __restrict__ B,
               const float* __restrict__ bias,
               const float* __restrict__ xproj, const float* __restrict__ hold,
               float* __restrict__ C, int M, int N, int K,
               const float* __restrict__ scale_ptr) {
    __shared__ float As[16][64];
    __shared__ float Bs[16][64];

    const int tid  = threadIdx.x;
    const int tx   = tid & 15;   // 0..15 -> n within tile
    const int ty   = tid >> 4;   // 0..15 -> m within tile
    const int m0   = blockIdx.y * 64;
    const int n0   = blockIdx.x * 64;
    const int lrow = tid >> 2;        // 0..63
    const int lk   = (tid & 3) << 2;  // 0,4,8,12

    const float* Ap = A + (size_t)(m0 + lrow) * K + lk;
    const bool bvalid = (n0 + lrow) < N;
    const float* Bp = B + (size_t)(n0 + lrow) * K + lk;

    float acc[4][4] = {};

    // prefetch first K-tile
    float4 av = *(const float4*)Ap;
    float4 bv = bvalid ? *(const float4*)Bp : make_float4(0.f, 0.f, 0.f, 0.f);

    for (int k0 = 0; k0 < K; k0 += 16) {
        As[lk + 0][lrow] = av.x; As[lk + 1][lrow] = av.y;
        As[lk + 2][lrow] = av.z; As[lk + 3][lrow] = av.w;
        Bs[lk + 0][lrow] = bv.x; Bs[lk + 1][lrow] = bv.y;
        Bs[lk + 2][lrow] = bv.z; Bs[lk + 3][lrow] = bv.w;
        __syncthreads();

        // prefetch next K-tile while computing this one
        if (k0 + 16 < K) {
            av = *(const float4*)(Ap + k0 + 16);
            bv = bvalid ? *(const float4*)(Bp + k0 + 16) : make_float4(0.f, 0.f, 0.f, 0.f);
        }

#pragma unroll
        for (int k = 0; k < 16; k++) {
            float4 a4 = *(const float4*)&As[k][ty << 2];
            float4 b4 = *(const float4*)&Bs[k][tx << 2];
            float ar[4] = {a4.x, a4.y, a4.z, a4.w};
            float br[4] = {b4.x, b4.y, b4.z, b4.w};
#pragma unroll
            for (int i = 0; i < 4; i++)
#pragma unroll
                for (int j = 0; j < 4; j++)
                    acc[i][j] = fmaf(ar[i], br[j], acc[i][j]);
        }
        __syncthreads();
    }

    const float scale = (MODE == 0) ? *scale_ptr : 1.0f;
#pragma unroll
    for (int i = 0; i < 4; i++) {
        const int m = m0 + (ty << 2) + i;
#pragma unroll
        for (int j = 0; j < 4; j++) {
            const int n = n0 + (tx << 2) + j;
            if (n >= N) continue;
            const size_t idx = (size_t)m * N + n;
            const float r = acc[i][j];
            if (MODE == 0) {
                C[idx] = fmaf(r, scale, bias[n]);
            } else if (MODE == 1) {
                const float pre = xproj[idx] + r + bias[n];
                C[idx] = (1.0f - ALPHA) * hold[idx] + ALPHA * tanhf(pre);
            } else {
                C[idx] = r + bias[n];
            }
        }
    }
}

// ---------------- host ----------------
extern "C" void kernel_launch(void* const* d_in, const int* in_sizes, int n_in,
                              void* d_out, int out_size) {
    const float* x     = (const float*)d_in[0];
    const float* Winw  = (const float*)d_in[1];
    const float* Winb  = (const float*)d_in[2];
    const float* u     = (const float*)d_in[3];
    const float* W0    = (const float*)d_in[4];
    const float* b0    = (const float*)d_in[5];
    const float* W1    = (const float*)d_in[6];
    const float* b1    = (const float*)d_in[7];
    const float* W2    = (const float*)d_in[8];
    const float* b2    = (const float*)d_in[9];
    const float* headw = (const float*)d_in[10];
    const float* headb = (const float*)d_in[11];
    float* out = (float*)d_out;

    float *t, *s, *scal, *xp, *hA, *hB;
    cudaGetSymbolAddress((void**)&t,    g_t);
    cudaGetSymbolAddress((void**)&s,    g_s);
    cudaGetSymbolAddress((void**)&scal, g_scal);
    cudaGetSymbolAddress((void**)&xp,   g_xproj);
    cudaGetSymbolAddress((void**)&hA,   g_hA);
    cudaGetSymbolAddress((void**)&hB,   g_hB);

    // h0 = 0
    zero_kernel<<<(BATCH * D_H + 255) / 256, 256>>>(hA, BATCH * D_H);

    // spectral-norm scalar: 1/sigma -> scal[1]
    matvec_t_kernel<<<D_IN / 256, 256>>>(Winw, u, t);
    reduce_t_kernel<<<1, 1024>>>(t, scal);
    matvec_s_kernel<<<64, 256>>>(Winw, t, scal, s);
    reduce_s_kernel<<<1, 1024>>>(s, scal);

    // x_proj = (x @ W_in^T) / sigma + b_in
    {
        dim3 grid(D_H / 64, BATCH / 64);
        gemm_nt_kernel<0><<<grid, 256>>>(x, Winw, Winb, nullptr, nullptr,
                                         xp, BATCH, D_H, D_IN, scal + 1);
    }

    // 30 steps x 3 layers, ping-pong h
    const float* Ws[3] = {W0, W1, W2};
    const float* bs[3] = {b0, b1, b2};
    float* cur = hA;
    float* nxt = hB;
    dim3 gstep(D_H / 64, BATCH / 64);
    for (int st = 0; st < STEPS; st++) {
        for (int l = 0; l < 3; l++) {
            gemm_nt_kernel<1><<<gstep, 256>>>(cur, Ws[l], bs[l], xp, cur,
                                              nxt, BATCH, D_H, D_H, nullptr);
            float* tmp = cur; cur = nxt; nxt = tmp;
        }
    }

    // head: out = h @ head_w^T + head_b
    {
        dim3 grid((D_OUT + 63) / 64, BATCH / 64);
        gemm_nt_kernel<2><<<grid, 256>>>(cur, headw, headb, nullptr, nullptr,
                                         out, BATCH, D_OUT, D_H, nullptr);
    }
}